// round 6
// baseline (speedup 1.0000x reference)
#include <cuda_runtime.h>

// CapsNet dynamic routing, B=64, IC=2048, ID=8, OC=32, OD=16, 3 routing iters.
// Strategy: never materialize u_hat (268MB). Three fused "passes" recompute
// u_hat from W (33.5MB, L2-resident) and x (4MB), each pass fuses:
//   agreement dot (u.v_prev) -> logits update -> softmax over o -> c*u accumulate.
// s accumulated in registers per block, written as per-block partials (no atomics),
// reduced + squashed in a tiny second kernel.

#define B_      64
#define IC_     2048
#define ID_     8
#define OC_     32
#define OD_     16
#define TI_     8              // i's per smem chunk
#define ICH_    (IC_ / TI_)    // 256 chunks
#define GX_     74             // i-stripe blocks (74 x 2 = 148 = one full wave)
#define THREADS_ 512
#define WPAD_   33             // padded o-stride (in float4) for conflict-free STS/LDS

// ---- device scratch (allocation-free: static globals) ----
__device__ float g_b[B_ * IC_ * OC_];              // routing logits b_ij (16.7MB)
__device__ float g_spart[GX_ * B_ * OC_ * OD_];    // per-i-stripe partial s (9.7MB)
__device__ float g_v[B_ * OC_ * OD_];              // v_j between passes

// ---- shared memory layout ----
#define WS_F4   (TI_ * 16 * 2 * WPAD_)             // 8448 float4 = 135168 B
#define XS_F    (32 * TI_ * ID_)                   // 2048 floats = 8192 B
#define VS_F    (32 * OD_ * OC_)                   // 16384 floats = 65536 B
#define SMEM_BYTES (WS_F4 * 16 + XS_F * 4 + VS_F * 4)   // 208896 B

__device__ __forceinline__ float warp_softmax32(float v) {
    float m = v;
    #pragma unroll
    for (int s = 16; s > 0; s >>= 1)
        m = fmaxf(m, __shfl_xor_sync(0xffffffffu, m, s));
    float e = __expf(v - m);
    float sum = e;
    #pragma unroll
    for (int s = 16; s > 0; s >>= 1)
        sum += __shfl_xor_sync(0xffffffffu, sum, s);
    return e / sum;
}

// PASS=0: c = 1/32 (softmax of zero logits), no agreement, no logit I/O.
// PASS=1: b = u.v0           ; store b ; c = softmax(b); accumulate c*u.
// PASS=2: b = g_b + u.v1     ;          c = softmax(b); accumulate c*u.
template <int PASS>
__global__ __launch_bounds__(THREADS_, 1)
void pass_kernel(const float* __restrict__ x, const float* __restrict__ W) {
    extern __shared__ char smem_raw[];
    float4* ws = reinterpret_cast<float4*>(smem_raw);                 // [il][j][dp][o(pad 33)]
    float*  xs = reinterpret_cast<float*>(smem_raw + WS_F4 * 16);     // [bl][il][d]
    float*  vs = xs + XS_F;                                           // [bl][j][o]

    const int tid = threadIdx.x;
    const int w   = tid >> 5;          // warp id: 0..15
    const int o   = tid & 31;          // lane = out capsule
    const int bx  = blockIdx.x;        // i-stripe id: 0..73
    const int bbase = blockIdx.y * 32; // batch half
    const int b0 = bbase + w;
    const int b1 = bbase + w + 16;

    // stage v (constant for the whole pass)
    if (PASS > 0) {
        #pragma unroll 1
        for (int e = tid; e < VS_F; e += THREADS_) {
            int oo = e & 31, j = (e >> 5) & 15, bl = e >> 9;
            vs[e] = g_v[((bbase + bl) * OC_ + oo) * OD_ + j];
        }
    }

    float s0[OD_], s1[OD_];
    #pragma unroll
    for (int j = 0; j < OD_; j++) { s0[j] = 0.f; s1[j] = 0.f; }

    #pragma unroll 1
    for (int ic = bx; ic < ICH_; ic += GX_) {
        const int i0 = ic * TI_;
        __syncthreads();   // previous chunk fully consumed (also covers vs staging)

        // stage W chunk with transpose: gmem [i][o][j][d] -> smem [il][j][dp][o] float4
        const float4* wg = reinterpret_cast<const float4*>(W + (size_t)i0 * OC_ * OD_ * ID_);
        #pragma unroll 1
        for (int e = tid; e < TI_ * OC_ * OD_ * 2; e += THREADS_) {
            int dp = e & 1, j = (e >> 1) & 15, oo = (e >> 5) & 31, il = e >> 10;
            ws[((il * 16 + j) * 2 + dp) * WPAD_ + oo] = wg[e];   // coalesced read
        }
        // stage x chunk: [bl][il][d]
        #pragma unroll 1
        for (int e = tid; e < 32 * TI_ * ID_; e += THREADS_) {
            int d = e & 7, il = (e >> 3) & (TI_ - 1), bl = e >> 6;
            xs[e] = x[(size_t)(bbase + bl) * IC_ * ID_ + (size_t)(i0 + il) * ID_ + d];
        }
        __syncthreads();

        #pragma unroll 1
        for (int il = 0; il < TI_; il++) {
            const int i = i0 + il;
            const float4* xpa = reinterpret_cast<const float4*>(xs + (w * TI_ + il) * ID_);
            const float4* xpb = reinterpret_cast<const float4*>(xs + ((w + 16) * TI_ + il) * ID_);
            const float4 xa0 = xpa[0], xa1 = xpa[1];
            const float4 xb0 = xpb[0], xb1 = xpb[1];

            float u0[OD_], u1[OD_];
            float a0 = 0.f, a1 = 0.f;

            #pragma unroll
            for (int j = 0; j < OD_; j++) {
                const float4* wr = ws + (il * 16 + j) * 2 * WPAD_;
                const float4 wa = wr[o];            // W[i,o,j,0..3]
                const float4 wb = wr[WPAD_ + o];    // W[i,o,j,4..7]
                float t0 = wa.x * xa0.x + wa.y * xa0.y + wa.z * xa0.z + wa.w * xa0.w
                         + wb.x * xa1.x + wb.y * xa1.y + wb.z * xa1.z + wb.w * xa1.w;
                float t1 = wa.x * xb0.x + wa.y * xb0.y + wa.z * xb0.z + wa.w * xb0.w
                         + wb.x * xb1.x + wb.y * xb1.y + wb.z * xb1.z + wb.w * xb1.w;
                u0[j] = t0;
                u1[j] = t1;
                if (PASS > 0) {
                    float vj0 = vs[(w * 16 + j) * 32 + o];
                    float vj1 = vs[((w + 16) * 16 + j) * 32 + o];
                    a0 = fmaf(t0, vj0, a0);
                    a1 = fmaf(t1, vj1, a1);
                }
            }

            float c0, c1;
            if (PASS == 0) {
                c0 = 1.0f / 32.0f;
                c1 = 1.0f / 32.0f;
            } else {
                const size_t ib0 = ((size_t)b0 * IC_ + i) * OC_ + o;
                const size_t ib1 = ((size_t)b1 * IC_ + i) * OC_ + o;
                float bb0 = a0, bb1 = a1;
                if (PASS == 2) { bb0 += g_b[ib0]; bb1 += g_b[ib1]; }
                if (PASS == 1) { g_b[ib0] = bb0; g_b[ib1] = bb1; }
                c0 = warp_softmax32(bb0);
                c1 = warp_softmax32(bb1);
            }

            #pragma unroll
            for (int j = 0; j < OD_; j++) {
                s0[j] = fmaf(c0, u0[j], s0[j]);
                s1[j] = fmaf(c1, u1[j], s1[j]);
            }
        }
    }

    // write per-stripe partials (deterministic, no atomics)
    {
        float4* p0 = reinterpret_cast<float4*>(g_spart + (((size_t)bx * B_ + b0) * OC_ + o) * OD_);
        float4* p1 = reinterpret_cast<float4*>(g_spart + (((size_t)bx * B_ + b1) * OC_ + o) * OD_);
        #pragma unroll
        for (int q = 0; q < 4; q++) {
            p0[q] = make_float4(s0[4 * q], s0[4 * q + 1], s0[4 * q + 2], s0[4 * q + 3]);
            p1[q] = make_float4(s1[4 * q], s1[4 * q + 1], s1[4 * q + 2], s1[4 * q + 3]);
        }
    }
}

template <bool FINAL>
__global__ void reduce_squash(float* __restrict__ out) {
    const int t = blockIdx.x * blockDim.x + threadIdx.x;   // (b, o): 0..2047
    if (t >= B_ * OC_) return;

    float s[OD_];
    #pragma unroll
    for (int j = 0; j < OD_; j++) s[j] = 0.f;

    const float4* base = reinterpret_cast<const float4*>(g_spart) + (size_t)t * 4;
    #pragma unroll 1
    for (int g = 0; g < GX_; g++) {
        const float4* p = base + (size_t)g * (B_ * OC_ * 4);
        float4 a = p[0], b = p[1], c = p[2], d = p[3];
        s[0] += a.x; s[1] += a.y; s[2]  += a.z; s[3]  += a.w;
        s[4] += b.x; s[5] += b.y; s[6]  += b.z; s[7]  += b.w;
        s[8] += c.x; s[9] += c.y; s[10] += c.z; s[11] += c.w;
        s[12] += d.x; s[13] += d.y; s[14] += d.z; s[15] += d.w;
    }

    float s2 = 0.f;
    #pragma unroll
    for (int j = 0; j < OD_; j++) s2 = fmaf(s[j], s[j], s2);
    const float scale = (s2 / (1.0f + s2)) * rsqrtf(s2 + 1e-9f);

    float* dst = FINAL ? (out + (size_t)t * OD_) : (g_v + (size_t)t * OD_);
    float4* dv = reinterpret_cast<float4*>(dst);
    #pragma unroll
    for (int q = 0; q < 4; q++)
        dv[q] = make_float4(s[4 * q] * scale, s[4 * q + 1] * scale,
                            s[4 * q + 2] * scale, s[4 * q + 3] * scale);
}

extern "C" void kernel_launch(void* const* d_in, const int* in_sizes, int n_in,
                              void* d_out, int out_size) {
    const float* x = (const float*)d_in[0];   // [64, 2048, 8]
    const float* W = (const float*)d_in[1];   // [1, 2048, 32, 16, 8]
    float* out = (float*)d_out;               // [64, 32, 16]
    (void)in_sizes; (void)n_in; (void)out_size;

    // Opt-in to >48KB dynamic smem. Host-side one-time init (deterministic,
    // no device work; runs on the first correctness call, before capture).
    static bool attr_done = false;
    if (!attr_done) {
        cudaFuncSetAttribute(pass_kernel<0>, cudaFuncAttributeMaxDynamicSharedMemorySize, SMEM_BYTES);
        cudaFuncSetAttribute(pass_kernel<1>, cudaFuncAttributeMaxDynamicSharedMemorySize, SMEM_BYTES);
        cudaFuncSetAttribute(pass_kernel<2>, cudaFuncAttributeMaxDynamicSharedMemorySize, SMEM_BYTES);
        attr_done = true;
    }

    const dim3 grid(GX_, 2);
    const dim3 rgrid((B_ * OC_ + 127) / 128);

    pass_kernel<0><<<grid, THREADS_, SMEM_BYTES>>>(x, W);
    reduce_squash<false><<<rgrid, 128>>>(nullptr);     // v0
    pass_kernel<1><<<grid, THREADS_, SMEM_BYTES>>>(x, W);
    reduce_squash<false><<<rgrid, 128>>>(nullptr);     // v1
    pass_kernel<2><<<grid, THREADS_, SMEM_BYTES>>>(x, W);
    reduce_squash<true><<<rgrid, 128>>>(out);          // v2 -> d_out
}

// round 7
// speedup vs baseline: 1.2200x; 1.2200x over previous
#include <cuda_runtime.h>

// CapsNet dynamic routing, B=64, IC=2048, ID=8, OC=32, OD=16, 3 routing iters.
// u_hat never materialized; 3 fused passes recompute it from W (L2-resident).
// R7: (A) reduce_squash -> 1 thread per (b,o,j), fully parallel/coalesced.
//     (B) pass kernels: 256 threads, 4 batches/warp, fma.rn.f32x2 packed math,
//         v staged as packed float2, g_v stored transposed [b][j][o].

#define B_      64
#define IC_     2048
#define ID_     8
#define OC_     32
#define OD_     16
#define TI_     8              // i's per smem chunk
#define ICH_    (IC_ / TI_)    // 256 chunks
#define GX_     74             // i-stripe blocks (74 x 2 = 148 = one wave)
#define THREADS_ 256
#define WPAD_   33             // padded o-stride (float4) for conflict-free LDS

typedef unsigned long long u64t;

// ---- device scratch (allocation-free) ----
__device__ float g_b[B_ * IC_ * OC_];              // routing logits (16.7MB)
__device__ float g_spart[GX_ * B_ * OC_ * OD_];    // per-stripe partial s (9.7MB)
__device__ float g_v2[B_ * OD_ * OC_];             // v transposed [b][j][o]

// ---- shared memory layout ----
#define WS_F4   (TI_ * 16 * 2 * WPAD_)             // 8448 float4 = 135168 B
#define XS_F    (32 * TI_ * ID_)                   // 2048 floats = 8192 B
#define VS_F2   (8 * 2 * 16 * 32)                  // 8192 float2 = 65536 B
#define SMEM_BYTES (WS_F4 * 16 + XS_F * 4 + VS_F2 * 8)   // 208896 B

// ---- packed f32x2 helpers ----
__device__ __forceinline__ u64t pack2(float lo, float hi) {
    u64t r; asm("mov.b64 %0, {%1, %2};" : "=l"(r) : "f"(lo), "f"(hi)); return r;
}
__device__ __forceinline__ void unpack2(u64t p, float& lo, float& hi) {
    asm("mov.b64 {%0, %1}, %2;" : "=f"(lo), "=f"(hi) : "l"(p));
}
__device__ __forceinline__ u64t ffma2(u64t a, u64t b, u64t c) {
    u64t d; asm("fma.rn.f32x2 %0, %1, %2, %3;" : "=l"(d) : "l"(a), "l"(b), "l"(c)); return d;
}
__device__ __forceinline__ u64t mul2(u64t a, u64t b) {
    u64t d; asm("mul.rn.f32x2 %0, %1, %2;" : "=l"(d) : "l"(a), "l"(b)); return d;
}
__device__ __forceinline__ u64t dup2(float v) { return pack2(v, v); }

// softmax denominator over 32 lanes (o). Logits are tiny (|b| < ~2): skip max-sub.
__device__ __forceinline__ float warp_expsum(float e) {
    float s = e;
    #pragma unroll
    for (int d = 16; d > 0; d >>= 1)
        s += __shfl_xor_sync(0xffffffffu, s, d);
    return s;
}

// PASS=0: c=1/32 (folded into partial store); no u array, no v, no logits.
// PASS=1: b = u.v0 ; store b ; c = softmax(b); s += c*u.
// PASS=2: b = g_b + u.v1 ;     c = softmax(b); s += c*u.
template <int PASS>
__global__ __launch_bounds__(THREADS_, 1)
void pass_kernel(const float* __restrict__ x, const float* __restrict__ W) {
    extern __shared__ char smem_raw[];
    float4* ws = reinterpret_cast<float4*>(smem_raw);                 // [il][j][dp][o pad33]
    float*  xs = reinterpret_cast<float*>(smem_raw + WS_F4 * 16);     // [bl][il][d]
    float2* vs = reinterpret_cast<float2*>(xs + XS_F);                // [w][pp][j][o] packed

    const int tid = threadIdx.x;
    const int w   = tid >> 5;          // warp 0..7
    const int o   = tid & 31;          // lane = out capsule
    const int bx  = blockIdx.x;
    const int bbase = blockIdx.y * 32;
    // 4 batches per warp, packed as pairs (A,B) and (C,D)
    const int bA = bbase + w;          // pair0.lo
    const int bB = bA + 8;             // pair0.hi
    const int bC = bA + 16;            // pair1.lo
    const int bD = bA + 24;            // pair1.hi

    if (PASS > 0) {
        // stage v as packed pairs; g_v2 is [b][j][o] so reads are coalesced
        #pragma unroll 4
        for (int e = tid; e < VS_F2; e += THREADS_) {
            int oo = e & 31, j = (e >> 5) & 15, pp = (e >> 9) & 1, ww = e >> 10;
            int blo = bbase + ww + pp * 16;
            vs[e] = make_float2(g_v2[(blo * OD_ + j) * OC_ + oo],
                                g_v2[((blo + 8) * OD_ + j) * OC_ + oo]);
        }
    }

    u64t s0[OD_], s1[OD_];
    #pragma unroll
    for (int j = 0; j < OD_; j++) { s0[j] = 0ull; s1[j] = 0ull; }

    #pragma unroll 1
    for (int ic = bx; ic < ICH_; ic += GX_) {
        const int i0 = ic * TI_;
        __syncthreads();   // prev chunk consumed (also covers vs staging)

        // stage W chunk: gmem [i][o][j][d] -> smem [il][j][dp][o]
        const float4* wg = reinterpret_cast<const float4*>(W + (size_t)i0 * OC_ * OD_ * ID_);
        #pragma unroll 4
        for (int e = tid; e < TI_ * OC_ * OD_ * 2; e += THREADS_) {
            int dp = e & 1, j = (e >> 1) & 15, oo = (e >> 5) & 31, il = e >> 10;
            ws[((il * 16 + j) * 2 + dp) * WPAD_ + oo] = wg[e];
        }
        // stage x chunk: [bl][il][d]
        #pragma unroll 4
        for (int e = tid; e < 32 * TI_ * ID_; e += THREADS_) {
            int d = e & 7, il = (e >> 3) & (TI_ - 1), bl = e >> 6;
            xs[e] = x[(size_t)(bbase + bl) * IC_ * ID_ + (size_t)(i0 + il) * ID_ + d];
        }
        __syncthreads();

        #pragma unroll 1
        for (int il = 0; il < TI_; il++) {
            const int i = i0 + il;

            // broadcast x loads for 4 batches, pack into batch-pairs
            const float4* xA = reinterpret_cast<const float4*>(xs + ((bA - bbase) * TI_ + il) * ID_);
            const float4* xB = reinterpret_cast<const float4*>(xs + ((bB - bbase) * TI_ + il) * ID_);
            const float4* xC = reinterpret_cast<const float4*>(xs + ((bC - bbase) * TI_ + il) * ID_);
            const float4* xD = reinterpret_cast<const float4*>(xs + ((bD - bbase) * TI_ + il) * ID_);
            const float4 a0 = xA[0], a1 = xA[1], b0f = xB[0], b1f = xB[1];
            const float4 c0f = xC[0], c1f = xC[1], d0f = xD[0], d1f = xD[1];
            u64t x20[8], x21[8];
            x20[0] = pack2(a0.x, b0f.x); x20[1] = pack2(a0.y, b0f.y);
            x20[2] = pack2(a0.z, b0f.z); x20[3] = pack2(a0.w, b0f.w);
            x20[4] = pack2(a1.x, b1f.x); x20[5] = pack2(a1.y, b1f.y);
            x20[6] = pack2(a1.z, b1f.z); x20[7] = pack2(a1.w, b1f.w);
            x21[0] = pack2(c0f.x, d0f.x); x21[1] = pack2(c0f.y, d0f.y);
            x21[2] = pack2(c0f.z, d0f.z); x21[3] = pack2(c0f.w, d0f.w);
            x21[4] = pack2(c1f.x, d1f.x); x21[5] = pack2(c1f.y, d1f.y);
            x21[6] = pack2(c1f.z, d1f.z); x21[7] = pack2(c1f.w, d1f.w);

            u64t u0[OD_], u1[OD_];
            u64t ag0 = 0ull, ag1 = 0ull;   // agreement accumulators (packed)

            #pragma unroll
            for (int j = 0; j < OD_; j++) {
                const float4* wr = ws + (il * 16 + j) * 2 * WPAD_;
                const float4 wa = wr[o];            // W[i,o,j,0..3]
                const float4 wb = wr[WPAD_ + o];    // W[i,o,j,4..7]
                u64t w0 = dup2(wa.x), w1 = dup2(wa.y), w2 = dup2(wa.z), w3 = dup2(wa.w);
                u64t w4 = dup2(wb.x), w5 = dup2(wb.y), w6 = dup2(wb.z), w7 = dup2(wb.w);

                if (PASS == 0) {
                    // accumulate straight into s (c folded in at store)
                    s0[j] = ffma2(w0, x20[0], s0[j]); s1[j] = ffma2(w0, x21[0], s1[j]);
                    s0[j] = ffma2(w1, x20[1], s0[j]); s1[j] = ffma2(w1, x21[1], s1[j]);
                    s0[j] = ffma2(w2, x20[2], s0[j]); s1[j] = ffma2(w2, x21[2], s1[j]);
                    s0[j] = ffma2(w3, x20[3], s0[j]); s1[j] = ffma2(w3, x21[3], s1[j]);
                    s0[j] = ffma2(w4, x20[4], s0[j]); s1[j] = ffma2(w4, x21[4], s1[j]);
                    s0[j] = ffma2(w5, x20[5], s0[j]); s1[j] = ffma2(w5, x21[5], s1[j]);
                    s0[j] = ffma2(w6, x20[6], s0[j]); s1[j] = ffma2(w6, x21[6], s1[j]);
                    s0[j] = ffma2(w7, x20[7], s0[j]); s1[j] = ffma2(w7, x21[7], s1[j]);
                } else {
                    u64t t0 = mul2(w0, x20[0]);
                    u64t t1 = mul2(w0, x21[0]);
                    t0 = ffma2(w1, x20[1], t0); t1 = ffma2(w1, x21[1], t1);
                    t0 = ffma2(w2, x20[2], t0); t1 = ffma2(w2, x21[2], t1);
                    t0 = ffma2(w3, x20[3], t0); t1 = ffma2(w3, x21[3], t1);
                    t0 = ffma2(w4, x20[4], t0); t1 = ffma2(w4, x21[4], t1);
                    t0 = ffma2(w5, x20[5], t0); t1 = ffma2(w5, x21[5], t1);
                    t0 = ffma2(w6, x20[6], t0); t1 = ffma2(w6, x21[6], t1);
                    t0 = ffma2(w7, x20[7], t0); t1 = ffma2(w7, x21[7], t1);
                    u0[j] = t0;
                    u1[j] = t1;
                    // agreement: packed v pair is one LDS.64
                    float2 v0p = vs[((w * 2 + 0) * 16 + j) * 32 + o];
                    float2 v1p = vs[((w * 2 + 1) * 16 + j) * 32 + o];
                    ag0 = ffma2(t0, pack2(v0p.x, v0p.y), ag0);
                    ag1 = ffma2(t1, pack2(v1p.x, v1p.y), ag1);
                }
            }

            if (PASS > 0) {
                float fA, fB, fC, fD;
                unpack2(ag0, fA, fB);
                unpack2(ag1, fC, fD);
                const size_t iA = ((size_t)bA * IC_ + i) * OC_ + o;
                const size_t iB = ((size_t)bB * IC_ + i) * OC_ + o;
                const size_t iC = ((size_t)bC * IC_ + i) * OC_ + o;
                const size_t iD = ((size_t)bD * IC_ + i) * OC_ + o;
                if (PASS == 2) {
                    fA += g_b[iA]; fB += g_b[iB]; fC += g_b[iC]; fD += g_b[iD];
                } else {
                    g_b[iA] = fA; g_b[iB] = fB; g_b[iC] = fC; g_b[iD] = fD;
                }
                float eA = __expf(fA), eB = __expf(fB), eC = __expf(fC), eD = __expf(fD);
                float cA = __fdividef(eA, warp_expsum(eA));
                float cB = __fdividef(eB, warp_expsum(eB));
                float cC = __fdividef(eC, warp_expsum(eC));
                float cD = __fdividef(eD, warp_expsum(eD));
                u64t cp0 = pack2(cA, cB), cp1 = pack2(cC, cD);
                #pragma unroll
                for (int j = 0; j < OD_; j++) {
                    s0[j] = ffma2(cp0, u0[j], s0[j]);
                    s1[j] = ffma2(cp1, u1[j], s1[j]);
                }
            }
        }
    }

    // write per-stripe partials: g_spart layout [stripe][b][o][j]
    {
        const u64t cinv = (PASS == 0) ? dup2(1.0f / 32.0f) : dup2(1.0f);
        float* pA = g_spart + (((size_t)bx * B_ + bA) * OC_ + o) * OD_;
        float* pB = g_spart + (((size_t)bx * B_ + bB) * OC_ + o) * OD_;
        float* pC = g_spart + (((size_t)bx * B_ + bC) * OC_ + o) * OD_;
        float* pD = g_spart + (((size_t)bx * B_ + bD) * OC_ + o) * OD_;
        #pragma unroll
        for (int j = 0; j < OD_; j++) {
            float vA, vB, vC, vD;
            if (PASS == 0) {
                unpack2(mul2(cinv, s0[j]), vA, vB);
                unpack2(mul2(cinv, s1[j]), vC, vD);
            } else {
                unpack2(s0[j], vA, vB);
                unpack2(s1[j], vC, vD);
            }
            pA[j] = vA; pB[j] = vB; pC[j] = vC; pD[j] = vD;
        }
    }
}

// one thread per (b,o,j): coalesced stripe-sum + 16-lane shfl reduce for |s|^2
template <bool FINAL>
__global__ void reduce_squash(float* __restrict__ out) {
    const int t = blockIdx.x * blockDim.x + threadIdx.x;   // 0..32767
    const int j = t & 15;

    float s = 0.f;
    const float* p = g_spart + t;
    #pragma unroll 2
    for (int g = 0; g < GX_; g++)
        s += p[(size_t)g * (B_ * OC_ * OD_)];

    float s2 = s * s;
    #pragma unroll
    for (int d = 1; d < 16; d <<= 1)
        s2 += __shfl_xor_sync(0xffffffffu, s2, d);

    const float scale = (s2 / (1.0f + s2)) * rsqrtf(s2 + 1e-9f);
    const float vj = s * scale;

    if (FINAL) {
        out[t] = vj;                                   // [b][o][j], coalesced
    } else {
        const int bo = t >> 4, b = bo >> 5, oo = bo & 31;
        g_v2[(b * OD_ + j) * OC_ + oo] = vj;           // transposed [b][j][o]
    }
}

extern "C" void kernel_launch(void* const* d_in, const int* in_sizes, int n_in,
                              void* d_out, int out_size) {
    const float* x = (const float*)d_in[0];   // [64, 2048, 8]
    const float* W = (const float*)d_in[1];   // [1, 2048, 32, 16, 8]
    float* out = (float*)d_out;               // [64, 32, 16]
    (void)in_sizes; (void)n_in; (void)out_size;

    static bool attr_done = false;
    if (!attr_done) {
        cudaFuncSetAttribute(pass_kernel<0>, cudaFuncAttributeMaxDynamicSharedMemorySize, SMEM_BYTES);
        cudaFuncSetAttribute(pass_kernel<1>, cudaFuncAttributeMaxDynamicSharedMemorySize, SMEM_BYTES);
        cudaFuncSetAttribute(pass_kernel<2>, cudaFuncAttributeMaxDynamicSharedMemorySize, SMEM_BYTES);
        attr_done = true;
    }

    const dim3 grid(GX_, 2);
    const dim3 rgrid(B_ * OC_ * OD_ / 256);   // 128 blocks x 256 threads

    pass_kernel<0><<<grid, THREADS_, SMEM_BYTES>>>(x, W);
    reduce_squash<false><<<rgrid, 256>>>(nullptr);     // v0 -> g_v2
    pass_kernel<1><<<grid, THREADS_, SMEM_BYTES>>>(x, W);
    reduce_squash<false><<<rgrid, 256>>>(nullptr);     // v1 -> g_v2
    pass_kernel<2><<<grid, THREADS_, SMEM_BYTES>>>(x, W);
    reduce_squash<true><<<rgrid, 256>>>(out);          // v2 -> d_out
}

// round 9
// speedup vs baseline: 2.1390x; 1.7533x over previous
#include <cuda_runtime.h>
#include <cstdint>

// CapsNet dynamic routing, B=64, IC=2048, ID=8, OC=32, OD=16, 3 routing iters.
// R8: j-pair f32x2 packing (dup operand = x, 4x fewer MOVs), cp.async
//     double-buffered W/x staging (TI=4), 4-way-parallel reduce_squash.

#define B_      64
#define IC_     2048
#define ID_     8
#define OC_     32
#define OD_     16
#define TI_     4              // i's per smem chunk
#define NCH_    (IC_ / TI_)    // 512 chunks
#define GX_     74             // i-stripe blocks; grid (74,2) = 148 = one wave
#define THREADS_ 256
#define JP_     8              // j pairs
#define WROW_   265            // float2 stride per (il,d): 8*33+1, bank-spreads staging

typedef unsigned long long u64t;

// ---- device scratch (allocation-free) ----
__device__ float g_b[B_ * IC_ * OC_];              // routing logits (16.7MB)
__device__ float g_spart[GX_ * B_ * OC_ * OD_];    // per-stripe partial s (9.7MB)
__device__ float g_v2[B_ * JP_ * OC_ * 2];         // v j-paired [b][jp][o]{j0,j1}

// ---- shared memory layout (bytes) ----
#define WBUF_F2   (TI_ * ID_ * WROW_)              // 8480 float2 = 67840 B per buffer
#define WS_BYTES  (2 * WBUF_F2 * 8)                // 135680
#define XBUF_F    (32 * TI_ * ID_)                 // 1024 floats per buffer
#define XS_BYTES  (2 * XBUF_F * 4)                 // 8192
#define VS_F2     (32 * JP_ * OC_)                 // 8192 float2 = 65536 B
#define SMEM_BYTES (WS_BYTES + XS_BYTES + VS_F2 * 8)   // 209408

// ---- f32x2 helpers ----
__device__ __forceinline__ u64t pack2(float lo, float hi) {
    u64t r; asm("mov.b64 %0, {%1, %2};" : "=l"(r) : "f"(lo), "f"(hi)); return r;
}
__device__ __forceinline__ void unpack2(u64t p, float& lo, float& hi) {
    asm("mov.b64 {%0, %1}, %2;" : "=f"(lo), "=f"(hi) : "l"(p));
}
__device__ __forceinline__ u64t ffma2(u64t a, u64t b, u64t c) {
    u64t d; asm("fma.rn.f32x2 %0, %1, %2, %3;" : "=l"(d) : "l"(a), "l"(b), "l"(c)); return d;
}
__device__ __forceinline__ u64t mul2(u64t a, u64t b) {
    u64t d; asm("mul.rn.f32x2 %0, %1, %2;" : "=l"(d) : "l"(a), "l"(b)); return d;
}
__device__ __forceinline__ u64t dup2(float v) { return pack2(v, v); }

__device__ __forceinline__ uint32_t smem_u32(const void* p) {
    uint32_t a;
    asm("{ .reg .u64 t; cvta.to.shared.u64 t, %1; cvt.u32.u64 %0, t; }" : "=r"(a) : "l"(p));
    return a;
}
__device__ __forceinline__ void cpa4(uint32_t dst, const float* src) {
    asm volatile("cp.async.ca.shared.global [%0], [%1], 4;" :: "r"(dst), "l"(src));
}
__device__ __forceinline__ void cpa16(uint32_t dst, const float* src) {
    asm volatile("cp.async.cg.shared.global [%0], [%1], 16;" :: "r"(dst), "l"(src));
}
__device__ __forceinline__ void cpa_commit() {
    asm volatile("cp.async.commit_group;" ::: "memory");
}
template <int N>
__device__ __forceinline__ void cpa_wait() {
    asm volatile("cp.async.wait_group %0;" :: "n"(N) : "memory");
}

__device__ __forceinline__ float warp_expsum(float e) {
    float s = e;
    #pragma unroll
    for (int d = 16; d > 0; d >>= 1)
        s += __shfl_xor_sync(0xffffffffu, s, d);
    return s;
}

// PASS=0: c=1/32 (accumulate u straight into s, scale at store); no logits/v.
// PASS=1: b = u.v0 ; store b ; c = softmax(b); s += c*u.
// PASS=2: b = g_b + u.v1 ;     c = softmax(b); s += c*u.
template <int PASS>
__global__ __launch_bounds__(THREADS_, 1)
void pass_kernel(const float* __restrict__ x, const float* __restrict__ W) {
    extern __shared__ char smem_raw[];
    float2* ws  = reinterpret_cast<float2*>(smem_raw);                  // 2 bufs W
    float*  xs  = reinterpret_cast<float*>(smem_raw + WS_BYTES);        // 2 bufs x
    float2* vsm = reinterpret_cast<float2*>(smem_raw + WS_BYTES + XS_BYTES);

    const int tid = threadIdx.x;
    const int w   = tid >> 5;          // warp 0..7
    const int o   = tid & 31;          // lane = out capsule
    const int bx  = blockIdx.x;
    const int bbase = blockIdx.y * 32;
    const int bl0 = w, bl1 = w + 8, bl2 = w + 16, bl3 = w + 24;  // local batches

    const uint32_t ws_u32 = smem_u32(ws);
    const uint32_t xs_u32 = smem_u32(xs);

    // stage v (j-paired float2 in g_v2, linear copy)
    if (PASS > 0) {
        const float2* gv = reinterpret_cast<const float2*>(g_v2) + bbase * (JP_ * OC_);
        #pragma unroll 8
        for (int e = tid; e < VS_F2; e += THREADS_) vsm[e] = gv[e];
    }

    u64t s2[4][JP_];
    #pragma unroll
    for (int b = 0; b < 4; b++)
        #pragma unroll
        for (int jp = 0; jp < JP_; jp++) s2[b][jp] = 0ull;

    // ---- staging lambda: W (4B transpose copies) + x (16B copies) ----
    auto stage = [&](int buf, int ic) {
        const int i0 = ic * TI_;
        const float* Wb = W + (size_t)i0 * (OC_ * OD_ * ID_);
        const uint32_t wdst_base = ws_u32 + buf * (WBUF_F2 * 8);
        #pragma unroll
        for (int k = 0; k < 64; k++) {
            int f = tid + k * THREADS_;            // 0..16383
            int d = f & 7, j = (f >> 3) & 15, oo = (f >> 7) & 31, il = f >> 12;
            uint32_t dst = wdst_base + (((il * ID_ + d) * WROW_ + (j >> 1) * 33 + oo) << 3)
                         + ((j & 1) << 2);
            cpa4(dst, Wb + f);
        }
        // x: 256 granules of 16B
        {
            int g = tid;
            int b_l = g >> 3, il = (g >> 1) & 3, dh = g & 1;
            const float* src = x + ((size_t)(bbase + b_l) * IC_ + (i0 + il)) * ID_ + dh * 4;
            uint32_t dst = xs_u32 + buf * (XBUF_F * 4) + (((b_l * TI_ + il) * ID_ + dh * 4) << 2);
            cpa16(dst, src);
        }
    };

    // ---- double-buffered chunk loop ----
    int ic = bx;
    stage(0, ic);
    cpa_commit();

    #pragma unroll 1
    for (int k = 0; ic < NCH_; ic += GX_, k++) {
        const int nxt = ic + GX_;
        if (nxt < NCH_) { stage((k + 1) & 1, nxt); cpa_commit(); cpa_wait<1>(); }
        else            { cpa_wait<0>(); }
        __syncthreads();

        const int buf = k & 1;
        const float2* wbuf = ws + buf * WBUF_F2;
        const float*  xbuf = xs + buf * XBUF_F;
        const int i0 = ic * TI_;

        #pragma unroll 1
        for (int il = 0; il < TI_; il++) {
            const int i = i0 + il;
            // x: 8 floats per batch
            const float4* xpA = reinterpret_cast<const float4*>(xbuf + (bl0 * TI_ + il) * ID_);
            const float4* xpB = reinterpret_cast<const float4*>(xbuf + (bl1 * TI_ + il) * ID_);
            const float4* xpC = reinterpret_cast<const float4*>(xbuf + (bl2 * TI_ + il) * ID_);
            const float4* xpD = reinterpret_cast<const float4*>(xbuf + (bl3 * TI_ + il) * ID_);
            float xA[8], xB[8], xC[8], xD[8];
            { float4 t0 = xpA[0], t1 = xpA[1];
              xA[0]=t0.x; xA[1]=t0.y; xA[2]=t0.z; xA[3]=t0.w; xA[4]=t1.x; xA[5]=t1.y; xA[6]=t1.z; xA[7]=t1.w; }
            { float4 t0 = xpB[0], t1 = xpB[1];
              xB[0]=t0.x; xB[1]=t0.y; xB[2]=t0.z; xB[3]=t0.w; xB[4]=t1.x; xB[5]=t1.y; xB[6]=t1.z; xB[7]=t1.w; }
            { float4 t0 = xpC[0], t1 = xpC[1];
              xC[0]=t0.x; xC[1]=t0.y; xC[2]=t0.z; xC[3]=t0.w; xC[4]=t1.x; xC[5]=t1.y; xC[6]=t1.z; xC[7]=t1.w; }
            { float4 t0 = xpD[0], t1 = xpD[1];
              xD[0]=t0.x; xD[1]=t0.y; xD[2]=t0.z; xD[3]=t0.w; xD[4]=t1.x; xD[5]=t1.y; xD[6]=t1.z; xD[7]=t1.w; }

            u64t u[4][JP_];

            #pragma unroll
            for (int d = 0; d < ID_; d++) {
                const u64t* wr = reinterpret_cast<const u64t*>(wbuf + (il * ID_ + d) * WROW_ + o);
                u64t wv[JP_];
                #pragma unroll
                for (int jp = 0; jp < JP_; jp++) wv[jp] = wr[jp * 33];   // {W[j],W[j+1]}
                const u64t xdA = dup2(xA[d]), xdB = dup2(xB[d]);
                const u64t xdC = dup2(xC[d]), xdD = dup2(xD[d]);
                if (PASS == 0) {
                    #pragma unroll
                    for (int jp = 0; jp < JP_; jp++) {
                        s2[0][jp] = ffma2(wv[jp], xdA, s2[0][jp]);
                        s2[1][jp] = ffma2(wv[jp], xdB, s2[1][jp]);
                        s2[2][jp] = ffma2(wv[jp], xdC, s2[2][jp]);
                        s2[3][jp] = ffma2(wv[jp], xdD, s2[3][jp]);
                    }
                } else if (d == 0) {
                    #pragma unroll
                    for (int jp = 0; jp < JP_; jp++) {
                        u[0][jp] = mul2(wv[jp], xdA);
                        u[1][jp] = mul2(wv[jp], xdB);
                        u[2][jp] = mul2(wv[jp], xdC);
                        u[3][jp] = mul2(wv[jp], xdD);
                    }
                } else {
                    #pragma unroll
                    for (int jp = 0; jp < JP_; jp++) {
                        u[0][jp] = ffma2(wv[jp], xdA, u[0][jp]);
                        u[1][jp] = ffma2(wv[jp], xdB, u[1][jp]);
                        u[2][jp] = ffma2(wv[jp], xdC, u[2][jp]);
                        u[3][jp] = ffma2(wv[jp], xdD, u[3][jp]);
                    }
                }
            }

            if (PASS > 0) {
                // agreement: ag_b = sum_j u*v (paired)
                u64t ag0 = 0ull, ag1 = 0ull, ag2 = 0ull, ag3 = 0ull;
                const u64t* vb0 = reinterpret_cast<const u64t*>(vsm + bl0 * (JP_ * OC_) + o);
                const u64t* vb1 = reinterpret_cast<const u64t*>(vsm + bl1 * (JP_ * OC_) + o);
                const u64t* vb2 = reinterpret_cast<const u64t*>(vsm + bl2 * (JP_ * OC_) + o);
                const u64t* vb3 = reinterpret_cast<const u64t*>(vsm + bl3 * (JP_ * OC_) + o);
                #pragma unroll
                for (int jp = 0; jp < JP_; jp++) {
                    ag0 = ffma2(u[0][jp], vb0[jp * OC_], ag0);
                    ag1 = ffma2(u[1][jp], vb1[jp * OC_], ag1);
                    ag2 = ffma2(u[2][jp], vb2[jp * OC_], ag2);
                    ag3 = ffma2(u[3][jp], vb3[jp * OC_], ag3);
                }
                float lo, hi, fA, fB, fC, fD;
                unpack2(ag0, lo, hi); fA = lo + hi;
                unpack2(ag1, lo, hi); fB = lo + hi;
                unpack2(ag2, lo, hi); fC = lo + hi;
                unpack2(ag3, lo, hi); fD = lo + hi;

                const size_t iA = ((size_t)(bbase + bl0) * IC_ + i) * OC_ + o;
                const size_t iB = ((size_t)(bbase + bl1) * IC_ + i) * OC_ + o;
                const size_t iC = ((size_t)(bbase + bl2) * IC_ + i) * OC_ + o;
                const size_t iD = ((size_t)(bbase + bl3) * IC_ + i) * OC_ + o;
                if (PASS == 2) {
                    fA += g_b[iA]; fB += g_b[iB]; fC += g_b[iC]; fD += g_b[iD];
                } else {
                    g_b[iA] = fA; g_b[iB] = fB; g_b[iC] = fC; g_b[iD] = fD;
                }
                const float eA = __expf(fA), eB = __expf(fB), eC = __expf(fC), eD = __expf(fD);
                const float cA = __fdividef(eA, warp_expsum(eA));
                const float cB = __fdividef(eB, warp_expsum(eB));
                const float cC = __fdividef(eC, warp_expsum(eC));
                const float cD = __fdividef(eD, warp_expsum(eD));
                const u64t c2A = dup2(cA), c2B = dup2(cB), c2C = dup2(cC), c2D = dup2(cD);
                #pragma unroll
                for (int jp = 0; jp < JP_; jp++) {
                    s2[0][jp] = ffma2(c2A, u[0][jp], s2[0][jp]);
                    s2[1][jp] = ffma2(c2B, u[1][jp], s2[1][jp]);
                    s2[2][jp] = ffma2(c2C, u[2][jp], s2[2][jp]);
                    s2[3][jp] = ffma2(c2D, u[3][jp], s2[3][jp]);
                }
            }
        }
        __syncthreads();   // all warps done with buf before it is restaged
    }

    // write per-stripe partials: g_spart [stripe][b][o][j]
    {
        const float sc = (PASS == 0) ? (1.0f / 32.0f) : 1.0f;
        const int bls[4] = {bl0, bl1, bl2, bl3};
        #pragma unroll
        for (int b = 0; b < 4; b++) {
            float4* dst = reinterpret_cast<float4*>(
                g_spart + (((size_t)bx * B_ + (bbase + bls[b])) * OC_ + o) * OD_);
            #pragma unroll
            for (int q = 0; q < 4; q++) {
                float l0, h0, l1, h1;
                unpack2(s2[b][2 * q], l0, h0);
                unpack2(s2[b][2 * q + 1], l1, h1);
                dst[q] = make_float4(l0 * sc, h0 * sc, l1 * sc, h1 * sc);
            }
        }
    }
}

// 4-way stripe-split reduce: 512 blocks x 256 threads.
// Block covers 64 elements (b,o,j); q = tid>>6 sums a stripe quarter.
template <bool FINAL>
__global__ void reduce_squash(float* __restrict__ out) {
    __shared__ float red[THREADS_];
    const int tid = threadIdx.x;
    const int q = tid >> 6;              // 0..3
    const int el = tid & 63;
    const int e = blockIdx.x * 64 + el;  // global element (b*512 + o*16 + j)

    // stripe ranges: q0:0-18, q1:19-37, q2:38-55, q3:56-73
    const int g0 = (q < 2) ? q * 19 : 38 + (q - 2) * 18;
    const int gn = (q < 2) ? 19 : 18;

    float s = 0.f;
    const float* p = g_spart + (size_t)g0 * (B_ * OC_ * OD_) + e;
    #pragma unroll 19
    for (int g = 0; g < gn; g++)
        s += p[(size_t)g * (B_ * OC_ * OD_)];

    red[tid] = s;
    __syncthreads();
    if (q == 0) {
        s = red[el] + red[64 + el] + red[128 + el] + red[192 + el];
        float s2 = s * s;
        #pragma unroll
        for (int d = 1; d < 16; d <<= 1)
            s2 += __shfl_xor_sync(0xffffffffu, s2, d);
        const float scale = (s2 / (1.0f + s2)) * rsqrtf(s2 + 1e-9f);
        const float vj = s * scale;
        if (FINAL) {
            out[e] = vj;                              // [b][o][j]
        } else {
            const int j = e & 15, bo = e >> 4, b = bo >> 5, oo = bo & 31;
            g_v2[(((b * JP_ + (j >> 1)) * OC_) + oo) * 2 + (j & 1)] = vj;
        }
    }
}

extern "C" void kernel_launch(void* const* d_in, const int* in_sizes, int n_in,
                              void* d_out, int out_size) {
    const float* x = (const float*)d_in[0];   // [64, 2048, 8]
    const float* W = (const float*)d_in[1];   // [1, 2048, 32, 16, 8]
    float* out = (float*)d_out;               // [64, 32, 16]
    (void)in_sizes; (void)n_in; (void)out_size;

    static bool attr_done = false;
    if (!attr_done) {
        cudaFuncSetAttribute(pass_kernel<0>, cudaFuncAttributeMaxDynamicSharedMemorySize, SMEM_BYTES);
        cudaFuncSetAttribute(pass_kernel<1>, cudaFuncAttributeMaxDynamicSharedMemorySize, SMEM_BYTES);
        cudaFuncSetAttribute(pass_kernel<2>, cudaFuncAttributeMaxDynamicSharedMemorySize, SMEM_BYTES);
        attr_done = true;
    }

    const dim3 grid(GX_, 2);
    const dim3 rgrid(B_ * OC_ * OD_ / 64);    // 512 blocks

    pass_kernel<0><<<grid, THREADS_, SMEM_BYTES>>>(x, W);
    reduce_squash<false><<<rgrid, THREADS_>>>(nullptr);   // v0 -> g_v2
    pass_kernel<1><<<grid, THREADS_, SMEM_BYTES>>>(x, W);
    reduce_squash<false><<<rgrid, THREADS_>>>(nullptr);   // v1 -> g_v2
    pass_kernel<2><<<grid, THREADS_, SMEM_BYTES>>>(x, W);
    reduce_squash<true><<<rgrid, THREADS_>>>(out);        // v2 -> d_out
}